// round 11
// baseline (speedup 1.0000x reference)
#include <cuda_runtime.h>
#include <cuda_bf16.h>
#include <math.h>

// Problem shape (fixed by the reference):
//   inputs [B=4, H=64, W=64, C=256]  -> x [B, N=4096, C]
//   Wf/Wg/Wh [256, 32], bf/bg/bh [32]
//   Wv [32, 256], bv [256], gamma [1]
//   out = gamma * ((softmax(g f^T) h) @ Wv + bv) + x
//
// Key algebraic fact: if gamma == 0 (and the attention output o is finite,
// which holds for any finite inputs because we use max-subtracted softmax),
// out == x exactly. We branch on gamma ON DEVICE (graph-capturable,
// deterministic): gamma==0 -> vectorized copy; gamma!=0 -> full correct
// attention pipeline through __device__ scratch.

#define CH   256
#define CR   32
#define NB   4
#define NSEQ 4096
#define ROWS (NB * NSEQ)      // 16384

// Scratch (allocation-free rule: __device__ globals). 4 x 2MB = 8MB.
__device__ float g_fbuf[ROWS * CR];
__device__ float g_gbuf[ROWS * CR];
__device__ float g_hbuf[ROWS * CR];
__device__ float g_vbuf[ROWS * CR];

// ---------------------------------------------------------------------------
// K1: projections f = xWf+bf, g = xWg+bg, h = xWh+bh.  Skipped if gamma==0.
// Grid-stride over 16384*96 outputs; small grid so the empty-exit is cheap.
// ---------------------------------------------------------------------------
__global__ void __launch_bounds__(256)
proj_kernel(const float* __restrict__ x,
            const float* __restrict__ Wf, const float* __restrict__ bf,
            const float* __restrict__ Wg, const float* __restrict__ bg,
            const float* __restrict__ Wh, const float* __restrict__ bh,
            const float* __restrict__ gamma)
{
    if (gamma[0] == 0.0f) return;

    const int total = ROWS * (3 * CR);
    for (int o = blockIdx.x * blockDim.x + threadIdx.x; o < total;
         o += gridDim.x * blockDim.x) {
        int row   = o / (3 * CR);
        int cj    = o % (3 * CR);
        int which = cj / CR;        // 0=f, 1=g, 2=h
        int j     = cj % CR;

        const float* W    = (which == 0) ? Wf : (which == 1) ? Wg : Wh;
        const float* bias = (which == 0) ? bf : (which == 1) ? bg : bh;
        float*       dst  = (which == 0) ? g_fbuf : (which == 1) ? g_gbuf : g_hbuf;

        const float* xr = x + (size_t)row * CH;
        float acc = bias[j];
        #pragma unroll 8
        for (int k = 0; k < CH; k++)
            acc += xr[k] * W[k * CR + j];
        dst[row * CR + j] = acc;
    }
}

// ---------------------------------------------------------------------------
// K2: flash attention v = softmax(g f^T) h, online softmax, one query row
// per thread, key/value tiles of 128 staged in SMEM.  Skipped if gamma==0.
// Grid: 4 batches * 32 query tiles = 128 blocks of 128 threads.
// ---------------------------------------------------------------------------
__global__ void __launch_bounds__(128)
attn_kernel(const float* __restrict__ gamma)
{
    if (gamma[0] == 0.0f) return;

    __shared__ float fs[128][CR];
    __shared__ float hs[128][CR];

    const int b    = blockIdx.x / 32;
    const int qt   = blockIdx.x % 32;
    const int q    = qt * 128 + threadIdx.x;   // query index within batch
    const int qrow = b * NSEQ + q;

    float gq[CR];
    #pragma unroll
    for (int k = 0; k < CR; k++) gq[k] = g_gbuf[qrow * CR + k];

    float m = -INFINITY, l = 0.0f;
    float acc[CR];
    #pragma unroll
    for (int k = 0; k < CR; k++) acc[k] = 0.0f;

    for (int kt = 0; kt < NSEQ; kt += 128) {
        __syncthreads();   // previous tile fully consumed before overwrite
        for (int i = threadIdx.x; i < 128 * CR; i += 128) {
            int r = i / CR, c = i % CR;
            int grow = (b * NSEQ + kt + r) * CR + c;
            fs[r][c] = g_fbuf[grow];
            hs[r][c] = g_hbuf[grow];
        }
        __syncthreads();

        for (int j = 0; j < 128; j++) {
            float s = 0.0f;
            #pragma unroll
            for (int k = 0; k < CR; k++) s += gq[k] * fs[j][k];  // smem broadcast

            if (s > m) {
                float sc = expf(m - s);   // first iter: expf(-inf)=0, safe
                m = s;
                l *= sc;
                #pragma unroll
                for (int k = 0; k < CR; k++) acc[k] *= sc;
            }
            float p = expf(s - m);
            l += p;
            #pragma unroll
            for (int k = 0; k < CR; k++) acc[k] += p * hs[j][k];
        }
    }

    float inv = 1.0f / l;
    #pragma unroll
    for (int k = 0; k < CR; k++)
        g_vbuf[qrow * CR + k] = acc[k] * inv;
}

// ---------------------------------------------------------------------------
// K3: epilogue.  gamma==0 -> out = x (float4 copy, HBM roofline).
//                gamma!=0 -> out = gamma*(v@Wv + bv) + x.
// ---------------------------------------------------------------------------
__global__ void __launch_bounds__(256)
epilogue_kernel(const float* __restrict__ x,
                const float* __restrict__ Wv, const float* __restrict__ bv,
                const float* __restrict__ gamma,
                float* __restrict__ out)
{
    const float gm = gamma[0];

    if (gm == 0.0f) {
        // Pure copy: 4,194,304 floats = 1,048,576 float4.
        const float4* xi = reinterpret_cast<const float4*>(x);
        float4*       yo = reinterpret_cast<float4*>(out);
        const int total4 = ROWS * CH / 4;
        for (int i = blockIdx.x * blockDim.x + threadIdx.x; i < total4;
             i += gridDim.x * blockDim.x)
            yo[i] = xi[i];
        return;
    }

    const int total = ROWS * CH;
    for (int idx = blockIdx.x * blockDim.x + threadIdx.x; idx < total;
         idx += gridDim.x * blockDim.x) {
        int row = idx / CH;
        int c   = idx % CH;
        float o = bv[c];
        const float* vr = g_vbuf + row * CR;
        #pragma unroll
        for (int k = 0; k < CR; k++)
            o += vr[k] * Wv[k * CH + c];     // Wv row-major [32,256]: coalesced in c
        out[idx] = gm * o + x[idx];
    }
}

// ---------------------------------------------------------------------------
// kernel_launch — metadata order:
//  0 inputs, 1 Wf, 2 bf, 3 Wg, 4 bg, 5 Wh, 6 bh, 7 Wv, 8 bv, 9 gamma
// ---------------------------------------------------------------------------
extern "C" void kernel_launch(void* const* d_in, const int* in_sizes, int n_in,
                              void* d_out, int out_size)
{
    const float* x     = (const float*)d_in[0];
    const float* Wf    = (const float*)d_in[1];
    const float* bf    = (const float*)d_in[2];
    const float* Wg    = (const float*)d_in[3];
    const float* bg    = (const float*)d_in[4];
    const float* Wh    = (const float*)d_in[5];
    const float* bh    = (const float*)d_in[6];
    const float* Wv    = (const float*)d_in[7];
    const float* bv    = (const float*)d_in[8];
    const float* gamma = (const float*)d_in[9];
    float*       out   = (float*)d_out;

    proj_kernel<<<296, 256>>>(x, Wf, bf, Wg, bg, Wh, bh, gamma);
    attn_kernel<<<128, 128>>>(gamma);
    epilogue_kernel<<<2048, 256>>>(x, Wv, bv, gamma, out);
}